// round 10
// baseline (speedup 1.0000x reference)
#include <cuda_runtime.h>

#define NN 50000
#define NE 1600000
#define NF 1433
#define NH 256
#define NC 7

// ------------------- scratch (static device globals; no runtime alloc) ----
__device__ int   g_cnt[NN];
__device__ int   g_rowptr[NN + 1];
__device__ int   g_cur[NN];
__device__ float g_dinv[NN];
__device__ int   g_col[NE];
__device__ int   g_is64;                  // 1 if edge_index is int64, else int32
__device__ float g_h [(size_t)NN * NH];   // x @ W1
__device__ float g_h1[(size_t)NN * NH];   // relu(agg1 + b1)
__device__ float g_g [NN * 8];            // h1 @ W2, padded stride 8

// ------------------- packed f32x2 helpers ----------------------------------
__device__ __forceinline__ unsigned long long pack_dup(float x) {
    unsigned long long r;
    asm("mov.b64 %0, {%1, %1};" : "=l"(r) : "f"(x));
    return r;
}
__device__ __forceinline__ void ffma2(unsigned long long &c,
                                      unsigned long long a,
                                      unsigned long long b) {
    asm("fma.rn.f32x2 %0, %1, %2, %0;" : "+l"(c) : "l"(a), "l"(b));
}
__device__ __forceinline__ float2 unpack2(unsigned long long v) {
    float2 r;
    asm("mov.b64 {%0, %1}, %2;" : "=f"(r.x), "=f"(r.y) : "l"(v));
    return r;
}

// ------------------- dtype detection ---------------------------------------
// int64 little-endian: odd 32-bit words of the first values are high halves of
// indices < 2^31 => all zero. int32 layout: random node ids.
__global__ void detect_kernel(const int* __restrict__ ei32) {
    if (threadIdx.x == 0 && blockIdx.x == 0) {
        int flag = 1;
        for (int i = 1; i < 200; i += 2)
            if (ei32[i] != 0) { flag = 0; break; }
        g_is64 = flag;
    }
}

__device__ __forceinline__ int edge_src(const int* ei32, int e) {
    return g_is64 ? ei32[2 * (size_t)e] : ei32[e];
}
__device__ __forceinline__ int edge_dst(const int* ei32, int e) {
    return g_is64 ? ei32[2 * ((size_t)NE + e)] : ei32[NE + e];
}

// ------------------- graph preprocessing ------------------------------------
__global__ void zero_cnt_kernel() {
    int i = blockIdx.x * blockDim.x + threadIdx.x;
    if (i < NN) g_cnt[i] = 0;
}

__global__ void count_kernel(const int* __restrict__ ei32) {
    int e = blockIdx.x * blockDim.x + threadIdx.x;
    if (e < NE) {
        int d = edge_dst(ei32, e);
        if ((unsigned)d < NN) atomicAdd(&g_cnt[d], 1);
    }
}

// chunked single-block scan: each thread owns CHUNK contiguous counts.
// Pass 1: local sums. One block-scan of 1024 partials. Pass 2: write prefixes.
#define SCAN_CHUNK 49   // 1024 * 49 = 50176 >= NN
__global__ void scan_kernel() {
    __shared__ int warp_sums[32];
    const int tid  = threadIdx.x;          // 1024
    const int lane = tid & 31, wid = tid >> 5;
    const int base = tid * SCAN_CHUNK;

    int local[SCAN_CHUNK];
    int sum = 0;
    #pragma unroll
    for (int j = 0; j < SCAN_CHUNK; j++) {
        int i = base + j;
        int v = (i < NN) ? g_cnt[i] : 0;
        local[j] = v;
        sum += v;
    }
    // block-wide exclusive scan of `sum`
    int x = sum;
    #pragma unroll
    for (int o = 1; o < 32; o <<= 1) {
        int t = __shfl_up_sync(0xffffffffu, x, o);
        if (lane >= o) x += t;
    }
    if (lane == 31) warp_sums[wid] = x;
    __syncthreads();
    if (tid < 32) {
        int y = warp_sums[tid];
        #pragma unroll
        for (int o = 1; o < 32; o <<= 1) {
            int t = __shfl_up_sync(0xffffffffu, y, o);
            if (tid >= o) y += t;
        }
        warp_sums[tid] = y;
    }
    __syncthreads();
    int excl = x - sum + (wid ? warp_sums[wid - 1] : 0);

    int run = excl;
    #pragma unroll
    for (int j = 0; j < SCAN_CHUNK; j++) {
        int i = base + j;
        if (i < NN) {
            g_rowptr[i] = run;
            g_cur[i]    = run;
            g_dinv[i]   = rsqrtf((float)(local[j] + 1));  // +1 = self loop
            run += local[j];
        }
    }
    if (tid == 1023) g_rowptr[NN] = run;
}

__global__ void fill_kernel(const int* __restrict__ ei32) {
    int e = blockIdx.x * blockDim.x + threadIdx.x;
    if (e < NE) {
        int s = edge_src(ei32, e);
        int d = edge_dst(ei32, e);
        if ((unsigned)s < NN && (unsigned)d < NN) {
            int p = atomicAdd(&g_cur[d], 1);
            if ((unsigned)p < NE) g_col[p] = s;
        }
    }
}

// ------------------- GEMM1: g_h = x[NN,NF] @ W1[NF,NH] ----------------------
// 128x128 tile / CTA, BK=16, double-buffered smem, packed f32x2 FMA.
__global__ void __launch_bounds__(256, 2) gemm1_kernel(const float* __restrict__ A,
                                                       const float* __restrict__ B) {
    __shared__ __align__(16) float As[2][16][132];   // As[buf][k][m]
    __shared__ __align__(16) float Bs[2][16][132];   // Bs[buf][k][n]
    const int tid  = threadIdx.x;
    const int tx   = tid & 15;
    const int ty   = tid >> 4;
    const int row0 = blockIdx.x * 128;
    const int col0 = blockIdx.y * 128;

    unsigned long long acc[8][4];
    #pragma unroll
    for (int i = 0; i < 8; i++)
        #pragma unroll
        for (int j = 0; j < 4; j++) acc[i][j] = 0ull;

    float  aR[8];
    float4 bR[2];
    const int bk  = tid >> 5;   // 0..7
    const int bn4 = tid & 31;

    const int nT = (NF + 15) / 16;  // 90

    // prologue: tile 0 -> buffer 0
    #pragma unroll
    for (int i = 0; i < 8; i++) {
        int r = row0 + ty + 16 * i;
        As[0][tx][ty + 16 * i] = (r < NN && tx < NF) ? A[(size_t)r * NF + tx] : 0.f;
    }
    #pragma unroll
    for (int i = 0; i < 2; i++) {
        int k = bk + 8 * i;
        float4 v = *(const float4*)&B[(size_t)k * NH + col0 + bn4 * 4];
        *(float4*)&Bs[0][k][bn4 * 4] = v;
    }
    __syncthreads();

    for (int t = 0; t < nT; t++) {
        const int buf = t & 1;
        if (t + 1 < nT) {
            int k0 = (t + 1) * 16;
            #pragma unroll
            for (int i = 0; i < 8; i++) {
                int r = row0 + ty + 16 * i;
                int k = k0 + tx;
                aR[i] = (r < NN && k < NF) ? A[(size_t)r * NF + k] : 0.f;
            }
            #pragma unroll
            for (int i = 0; i < 2; i++) {
                int k = k0 + bk + 8 * i;
                bR[i] = (k < NF) ? *(const float4*)&B[(size_t)k * NH + col0 + bn4 * 4]
                                 : make_float4(0.f, 0.f, 0.f, 0.f);
            }
        }
        #pragma unroll
        for (int k = 0; k < 16; k++) {
            float4 a0 = *(const float4*)&As[buf][k][ty * 8];
            float4 a1 = *(const float4*)&As[buf][k][ty * 8 + 4];
            ulonglong2 b0 = *(const ulonglong2*)&Bs[buf][k][tx * 8];
            ulonglong2 b1 = *(const ulonglong2*)&Bs[buf][k][tx * 8 + 4];
            float a[8] = {a0.x, a0.y, a0.z, a0.w, a1.x, a1.y, a1.z, a1.w};
            unsigned long long bp[4] = {b0.x, b0.y, b1.x, b1.y};
            #pragma unroll
            for (int i = 0; i < 8; i++) {
                unsigned long long ad = pack_dup(a[i]);
                #pragma unroll
                for (int j = 0; j < 4; j++) ffma2(acc[i][j], ad, bp[j]);
            }
        }
        if (t + 1 < nT) {
            int nb = (t + 1) & 1;
            #pragma unroll
            for (int i = 0; i < 8; i++) As[nb][tx][ty + 16 * i] = aR[i];
            #pragma unroll
            for (int i = 0; i < 2; i++) *(float4*)&Bs[nb][bk + 8 * i][bn4 * 4] = bR[i];
        }
        __syncthreads();
    }

    #pragma unroll
    for (int i = 0; i < 8; i++) {
        int r = row0 + ty * 8 + i;
        if (r < NN) {
            float2 v0 = unpack2(acc[i][0]);
            float2 v1 = unpack2(acc[i][1]);
            float2 v2 = unpack2(acc[i][2]);
            float2 v3 = unpack2(acc[i][3]);
            float* dst = &g_h[(size_t)r * NH + col0 + tx * 8];
            *(float4*)dst       = make_float4(v0.x, v0.y, v1.x, v1.y);
            *(float4*)(dst + 4) = make_float4(v2.x, v2.y, v3.x, v3.y);
        }
    }
}

// ------------------- aggregation layer 1 (CSR gather, no atomics) -----------
// h1[i] = relu( dinv[i] * sum_{s in N(i)} dinv[s]*h[s] + dinv[i]^2*h[i] + b1 )
__global__ void agg1_kernel(const float* __restrict__ b1) {
    __shared__ int   scol[128];
    __shared__ float snrm[128];
    const int i = blockIdx.x;
    const int f = threadIdx.x;   // 256 = NH
    const int start = g_rowptr[i];
    const int end   = g_rowptr[i + 1];
    float acc = 0.f;
    for (int p0 = start; p0 < end; p0 += 128) {
        int n = min(128, end - p0);
        if (f < n) {
            int s = g_col[p0 + f];
            scol[f] = s;
            snrm[f] = g_dinv[s];
        }
        __syncthreads();
        int j = 0;
        for (; j + 4 <= n; j += 4) {
            int s0 = scol[j], s1 = scol[j + 1], s2 = scol[j + 2], s3 = scol[j + 3];
            float w0 = snrm[j], w1 = snrm[j + 1], w2 = snrm[j + 2], w3 = snrm[j + 3];
            float h0  = g_h[(size_t)s0 * NH + f];
            float h1v = g_h[(size_t)s1 * NH + f];
            float h2  = g_h[(size_t)s2 * NH + f];
            float h3  = g_h[(size_t)s3 * NH + f];
            acc = fmaf(w0, h0, acc);
            acc = fmaf(w1, h1v, acc);
            acc = fmaf(w2, h2, acc);
            acc = fmaf(w3, h3, acc);
        }
        for (; j < n; j++)
            acc = fmaf(snrm[j], g_h[(size_t)scol[j] * NH + f], acc);
        __syncthreads();
    }
    float di = g_dinv[i];
    float v  = fmaf(di, acc, di * di * g_h[(size_t)i * NH + f]) + b1[f];
    g_h1[(size_t)i * NH + f] = fmaxf(v, 0.f);
}

// ------------------- GEMM2: g_g = h1[NN,256] @ W2[256,7] --------------------
__global__ void gemm2_kernel(const float* __restrict__ W2) {
    __shared__ float sW[NH * NC];
    const int tid = threadIdx.x;   // 256 threads, 8 warps, 1 node/warp
    for (int t = tid; t < NH * NC; t += 256) sW[t] = W2[t];
    __syncthreads();
    const int lane = tid & 31;
    const int node = blockIdx.x * 8 + (tid >> 5);
    float p[NC];
    #pragma unroll
    for (int j = 0; j < NC; j++) p[j] = 0.f;
    #pragma unroll
    for (int u = 0; u < 8; u++) {
        int k = u * 32 + lane;
        float v = g_h1[(size_t)node * NH + k];
        #pragma unroll
        for (int j = 0; j < NC; j++) p[j] = fmaf(v, sW[k * NC + j], p[j]);
    }
    #pragma unroll
    for (int o = 16; o > 0; o >>= 1)
        #pragma unroll
        for (int j = 0; j < NC; j++) p[j] += __shfl_down_sync(0xffffffffu, p[j], o);
    if (lane == 0) {
        #pragma unroll
        for (int j = 0; j < NC; j++) g_g[node * 8 + j] = p[j];
        g_g[node * 8 + 7] = 0.f;
    }
}

// ------------------- aggregation layer 2 (7-wide, CSR gather) ---------------
__global__ void agg2_kernel(const float* __restrict__ b2, float* __restrict__ out) {
    const int tid  = threadIdx.x;            // 256 = 32 nodes x 8 threads
    const int node = blockIdx.x * 32 + (tid >> 3);
    const int j    = tid & 7;
    if (node >= NN) return;
    const int start = g_rowptr[node], end = g_rowptr[node + 1];
    float acc = 0.f;
    for (int p = start; p < end; p++) {
        int s = g_col[p];
        acc = fmaf(g_dinv[s], g_g[s * 8 + j], acc);
    }
    float di = g_dinv[node];
    float v  = fmaf(di, acc, di * di * g_g[node * 8 + j]);
    if (j < NC) out[node * NC + j] = v + b2[j];
}

// ------------------- launch --------------------------------------------------
extern "C" void kernel_launch(void* const* d_in, const int* in_sizes, int n_in,
                              void* d_out, int out_size) {
    const float* x    = (const float*)d_in[0];
    const int*   ei32 = (const int*)d_in[1];   // int32 OR int64 (auto-detected)
    const float* W1   = (const float*)d_in[2];
    const float* b1   = (const float*)d_in[3];
    const float* W2   = (const float*)d_in[4];
    const float* b2   = (const float*)d_in[5];
    float*       out  = (float*)d_out;

    detect_kernel<<<1, 32>>>(ei32);
    zero_cnt_kernel<<<(NN + 255) / 256, 256>>>();
    count_kernel<<<(NE + 255) / 256, 256>>>(ei32);
    scan_kernel<<<1, 1024>>>();
    fill_kernel<<<(NE + 255) / 256, 256>>>(ei32);

    dim3 g1((NN + 127) / 128, NH / 128);
    gemm1_kernel<<<g1, 256>>>(x, W1);

    agg1_kernel<<<NN, 256>>>(b1);
    gemm2_kernel<<<NN / 8, 256>>>(W2);
    agg2_kernel<<<(NN + 31) / 32, 256>>>(b2, out);
}

// round 12
// speedup vs baseline: 1.0618x; 1.0618x over previous
#include <cuda_runtime.h>
#include <cuda_bf16.h>
#include <cstdint>

#define NN 50000
#define NE 1600000
#define NF 1433
#define NH 256
#define NC 7
#define NT_K 90                  // ceil(NF/16)

// ------------------- scratch (static device globals; no runtime alloc) ----
__device__ int   g_cnt[NN];
__device__ int   g_rowptr[NN + 1];
__device__ int   g_cur[NN];
__device__ float g_dinv[NN];
__device__ int   g_col[NE];
__device__ int   g_is64;
__device__ float g_h [(size_t)NN * NH];   // x @ W1
__device__ float g_h1[(size_t)NN * NH];   // relu(agg1 + b1)
__device__ float g_g [NN * 8];            // h1 @ W2, padded stride 8

// ------------------- mma/ldmatrix helpers (sm_80 baseline ISA) -------------
__device__ __forceinline__ uint32_t smem_u32(const void* p) {
    uint32_t a;
    asm("{ .reg .u64 t; cvta.to.shared.u64 t, %1; cvt.u32.u64 %0, t; }"
        : "=r"(a) : "l"(p));
    return a;
}
__device__ __forceinline__ void ldsm_x4(uint32_t* r, uint32_t a) {
    asm volatile("ldmatrix.sync.aligned.m8n8.x4.shared.b16 {%0,%1,%2,%3}, [%4];"
                 : "=r"(r[0]), "=r"(r[1]), "=r"(r[2]), "=r"(r[3]) : "r"(a));
}
__device__ __forceinline__ void ldsm_x4_t(uint32_t* r, uint32_t a) {
    asm volatile("ldmatrix.sync.aligned.m8n8.x4.trans.shared.b16 {%0,%1,%2,%3}, [%4];"
                 : "=r"(r[0]), "=r"(r[1]), "=r"(r[2]), "=r"(r[3]) : "r"(a));
}
__device__ __forceinline__ void mma16816(float* d, const uint32_t* a, const uint32_t* b) {
    asm volatile("mma.sync.aligned.m16n8k16.row.col.f32.bf16.bf16.f32 "
                 "{%0,%1,%2,%3}, {%4,%5,%6,%7}, {%8,%9}, {%0,%1,%2,%3};"
                 : "+f"(d[0]), "+f"(d[1]), "+f"(d[2]), "+f"(d[3])
                 : "r"(a[0]), "r"(a[1]), "r"(a[2]), "r"(a[3]), "r"(b[0]), "r"(b[1]));
}

// ------------------- dtype detection ---------------------------------------
__global__ void detect_kernel(const int* __restrict__ ei32) {
    if (threadIdx.x == 0 && blockIdx.x == 0) {
        int flag = 1;
        for (int i = 1; i < 200; i += 2)
            if (ei32[i] != 0) { flag = 0; break; }
        g_is64 = flag;
    }
}
__device__ __forceinline__ int edge_src(const int* ei32, int e) {
    return g_is64 ? ei32[2 * (size_t)e] : ei32[e];
}
__device__ __forceinline__ int edge_dst(const int* ei32, int e) {
    return g_is64 ? ei32[2 * ((size_t)NE + e)] : ei32[NE + e];
}

// ------------------- graph preprocessing ------------------------------------
__global__ void zero_cnt_kernel() {
    int i = blockIdx.x * blockDim.x + threadIdx.x;
    if (i < NN) g_cnt[i] = 0;
}
__global__ void count_kernel(const int* __restrict__ ei32) {
    int e = blockIdx.x * blockDim.x + threadIdx.x;
    if (e < NE) {
        int d = edge_dst(ei32, e);
        if ((unsigned)d < NN) atomicAdd(&g_cnt[d], 1);
    }
}
// R9 multi-pass scan (known-good, regs=29)
__global__ void scan_kernel() {
    __shared__ int warp_sums[32];
    __shared__ int s_carry;
    const int tid  = threadIdx.x;          // 1024
    const int lane = tid & 31, wid = tid >> 5;
    if (tid == 0) s_carry = 0;
    __syncthreads();
    for (int base = 0; base < NN; base += 1024) {
        int i = base + tid;
        int v = (i < NN) ? g_cnt[i] : 0;
        int x = v;
        #pragma unroll
        for (int o = 1; o < 32; o <<= 1) {
            int t = __shfl_up_sync(0xffffffffu, x, o);
            if (lane >= o) x += t;
        }
        if (lane == 31) warp_sums[wid] = x;
        __syncthreads();
        if (tid < 32) {
            int y = warp_sums[tid];
            #pragma unroll
            for (int o = 1; o < 32; o <<= 1) {
                int t = __shfl_up_sync(0xffffffffu, y, o);
                if (tid >= o) y += t;
            }
            warp_sums[tid] = y;
        }
        __syncthreads();
        int incl = x + (wid ? warp_sums[wid - 1] : 0);
        int excl = incl - v + s_carry;
        if (i < NN) {
            g_rowptr[i] = excl;
            g_cur[i]    = excl;
            g_dinv[i]   = rsqrtf((float)(v + 1));
        }
        __syncthreads();
        if (tid == 1023) s_carry += incl;
        __syncthreads();
    }
    if (tid == 0) g_rowptr[NN] = s_carry;
}
__global__ void fill_kernel(const int* __restrict__ ei32) {
    int e = blockIdx.x * blockDim.x + threadIdx.x;
    if (e < NE) {
        int s = edge_src(ei32, e);
        int d = edge_dst(ei32, e);
        if ((unsigned)s < NN && (unsigned)d < NN) {
            int p = atomicAdd(&g_cur[d], 1);
            if ((unsigned)p < NE) g_col[p] = s;
        }
    }
}

// ------------------- GEMM1: g_h = x @ W1 via HMMA bf16 3-pass ---------------
// CTA tile 128x128, 8 warps (warp = 32m x 64n), K-step 16, double-buffered.
// smem per stage: Ah/Al [128m][16k] pitch 24 b16; Bh/Bl [16k][128n] pitch 136 b16.
#define ST_AH 0
#define ST_AL 6144
#define ST_BH 12288
#define ST_BL 16640
#define ST_SZ 20992

__global__ void __launch_bounds__(256) mma_gemm1_kernel(const float* __restrict__ A,
                                                        const float* __restrict__ B) {
    __shared__ __align__(16) char smem[2 * ST_SZ];
    const uint32_t sb = smem_u32(smem);
    const int tid  = threadIdx.x;
    const int lane = tid & 31, wid = tid >> 5;
    const int row0 = blockIdx.y * 128;
    const int col0 = blockIdx.x * 128;
    const int wm = wid & 3;        // 4 m-groups of 32
    const int wn = wid >> 2;       // 2 n-groups of 64

    float acc[2][8][4];
    #pragma unroll
    for (int i = 0; i < 2; i++)
        #pragma unroll
        for (int j = 0; j < 8; j++)
            #pragma unroll
            for (int r = 0; r < 4; r++) acc[i][j][r] = 0.f;

    // per-thread load roles
    const int a_r0 = tid >> 2, a_c = tid & 3;            // + q*64 rows
    const int b_kk = tid >> 4, b_nn = (tid & 15) * 8;

    float av[2][4];
    float bv[8];

    // ---- prologue: stage 0 direct --------------------------------------
    {
        #pragma unroll
        for (int q = 0; q < 2; q++) {
            int r = a_r0 + q * 64;
            int row = row0 + r;
            #pragma unroll
            for (int j = 0; j < 4; j++) {
                int k = a_c * 4 + j;
                av[q][j] = (row < NN && k < NF) ? A[(size_t)row * NF + k] : 0.f;
            }
        }
        if (b_kk < NF) {
            float4 v0 = *(const float4*)&B[(size_t)b_kk * NH + col0 + b_nn];
            float4 v1 = *(const float4*)&B[(size_t)b_kk * NH + col0 + b_nn + 4];
            bv[0]=v0.x; bv[1]=v0.y; bv[2]=v0.z; bv[3]=v0.w;
            bv[4]=v1.x; bv[5]=v1.y; bv[6]=v1.z; bv[7]=v1.w;
        } else {
            #pragma unroll
            for (int j = 0; j < 8; j++) bv[j] = 0.f;
        }
        // store stage 0
        char* st = smem;
        #pragma unroll
        for (int q = 0; q < 2; q++) {
            int r = a_r0 + q * 64;
            __nv_bfloat16 h[4], l[4];
            #pragma unroll
            for (int j = 0; j < 4; j++) {
                h[j] = __float2bfloat16(av[q][j]);
                l[j] = __float2bfloat16(av[q][j] - __bfloat162float(h[j]));
            }
            *(uint2*)(st + ST_AH + r * 48 + a_c * 8) = *(uint2*)h;
            *(uint2*)(st + ST_AL + r * 48 + a_c * 8) = *(uint2*)l;
        }
        {
            __nv_bfloat16 h[8], l[8];
            #pragma unroll
            for (int j = 0; j < 8; j++) {
                h[j] = __float2bfloat16(bv[j]);
                l[j] = __float2bfloat16(bv[j] - __bfloat162float(h[j]));
            }
            *(uint4*)(st + ST_BH + b_kk * 272 + b_nn * 2) = *(uint4*)h;
            *(uint4*)(st + ST_BL + b_kk * 272 + b_nn * 2) = *(uint4*)l;
        }
    }
    __syncthreads();

    // ldmatrix lane addressing
    const uint32_t a_lrow = (lane & 15);
    const uint32_t a_lcb  = (uint32_t)(lane >> 4) << 4;
    const uint32_t b_lk   = (lane & 7) + ((lane & 8) ? 8 : 0);
    const uint32_t b_ln   = (lane & 16) ? 8 : 0;

    for (int t = 0; t < NT_K; t++) {
        const int buf = t & 1;
        const bool more = (t + 1 < NT_K);

        // ---- prefetch next stage into regs ----
        if (more) {
            int k0 = (t + 1) * 16;
            #pragma unroll
            for (int q = 0; q < 2; q++) {
                int r = a_r0 + q * 64;
                int row = row0 + r;
                #pragma unroll
                for (int j = 0; j < 4; j++) {
                    int k = k0 + a_c * 4 + j;
                    av[q][j] = (row < NN && k < NF) ? A[(size_t)row * NF + k] : 0.f;
                }
            }
            int k = k0 + b_kk;
            if (k < NF) {
                float4 v0 = *(const float4*)&B[(size_t)k * NH + col0 + b_nn];
                float4 v1 = *(const float4*)&B[(size_t)k * NH + col0 + b_nn + 4];
                bv[0]=v0.x; bv[1]=v0.y; bv[2]=v0.z; bv[3]=v0.w;
                bv[4]=v1.x; bv[5]=v1.y; bv[6]=v1.z; bv[7]=v1.w;
            } else {
                #pragma unroll
                for (int j = 0; j < 8; j++) bv[j] = 0.f;
            }
        }

        // ---- compute: 3 terms (AhBh, AhBl, AlBh) ----
        const uint32_t base = sb + (uint32_t)buf * ST_SZ;
        #pragma unroll
        for (int term = 0; term < 3; term++) {
            const uint32_t Aoff = (term == 2) ? ST_AL : ST_AH;
            const uint32_t Boff = (term == 1) ? ST_BL : ST_BH;
            uint32_t a0[4], a1[4];
            uint32_t aaddr = base + Aoff + (wm * 32 + a_lrow) * 48 + a_lcb;
            ldsm_x4(a0, aaddr);
            ldsm_x4(a1, aaddr + 16 * 48);
            #pragma unroll
            for (int jj = 0; jj < 4; jj++) {
                uint32_t b[4];
                uint32_t baddr = base + Boff + b_lk * 272 +
                                 (uint32_t)(wn * 64 + jj * 16 + b_ln) * 2;
                ldsm_x4_t(b, baddr);
                mma16816(acc[0][2 * jj],     a0, b);
                mma16816(acc[0][2 * jj + 1], a0, b + 2);
                mma16816(acc[1][2 * jj],     a1, b);
                mma16816(acc[1][2 * jj + 1], a1, b + 2);
            }
        }

        // ---- store prefetched stage ----
        if (more) {
            char* st = smem + (buf ^ 1) * ST_SZ;
            #pragma unroll
            for (int q = 0; q < 2; q++) {
                int r = a_r0 + q * 64;
                __nv_bfloat16 h[4], l[4];
                #pragma unroll
                for (int j = 0; j < 4; j++) {
                    h[j] = __float2bfloat16(av[q][j]);
                    l[j] = __float2bfloat16(av[q][j] - __bfloat162float(h[j]));
                }
                *(uint2*)(st + ST_AH + r * 48 + a_c * 8) = *(uint2*)h;
                *(uint2*)(st + ST_AL + r * 48 + a_c * 8) = *(uint2*)l;
            }
            {
                __nv_bfloat16 h[8], l[8];
                #pragma unroll
                for (int j = 0; j < 8; j++) {
                    h[j] = __float2bfloat16(bv[j]);
                    l[j] = __float2bfloat16(bv[j] - __bfloat162float(h[j]));
                }
                *(uint4*)(st + ST_BH + b_kk * 272 + b_nn * 2) = *(uint4*)h;
                *(uint4*)(st + ST_BL + b_kk * 272 + b_nn * 2) = *(uint4*)l;
            }
        }
        __syncthreads();
    }

    // ---- epilogue ----
    #pragma unroll
    for (int i = 0; i < 2; i++) {
        int row = row0 + wm * 32 + i * 16 + (lane >> 2);
        #pragma unroll
        for (int j = 0; j < 8; j++) {
            int colb = col0 + wn * 64 + j * 8 + (lane & 3) * 2;
            if (row < NN)
                *(float2*)&g_h[(size_t)row * NH + colb] =
                    make_float2(acc[i][j][0], acc[i][j][1]);
            if (row + 8 < NN)
                *(float2*)&g_h[(size_t)(row + 8) * NH + colb] =
                    make_float2(acc[i][j][2], acc[i][j][3]);
        }
    }
}

// ------------------- aggregation layer 1 (CSR gather, no atomics) -----------
__global__ void agg1_kernel(const float* __restrict__ b1) {
    __shared__ int   scol[128];
    __shared__ float snrm[128];
    const int i = blockIdx.x;
    const int f = threadIdx.x;   // 256 = NH
    const int start = g_rowptr[i];
    const int end   = g_rowptr[i + 1];
    float acc = 0.f;
    for (int p0 = start; p0 < end; p0 += 128) {
        int n = min(128, end - p0);
        if (f < n) {
            int s = g_col[p0 + f];
            scol[f] = s;
            snrm[f] = g_dinv[s];
        }
        __syncthreads();
        int j = 0;
        for (; j + 4 <= n; j += 4) {
            int s0 = scol[j], s1 = scol[j + 1], s2 = scol[j + 2], s3 = scol[j + 3];
            float w0 = snrm[j], w1 = snrm[j + 1], w2 = snrm[j + 2], w3 = snrm[j + 3];
            float h0  = g_h[(size_t)s0 * NH + f];
            float h1v = g_h[(size_t)s1 * NH + f];
            float h2  = g_h[(size_t)s2 * NH + f];
            float h3  = g_h[(size_t)s3 * NH + f];
            acc = fmaf(w0, h0, acc);
            acc = fmaf(w1, h1v, acc);
            acc = fmaf(w2, h2, acc);
            acc = fmaf(w3, h3, acc);
        }
        for (; j < n; j++)
            acc = fmaf(snrm[j], g_h[(size_t)scol[j] * NH + f], acc);
        __syncthreads();
    }
    float di = g_dinv[i];
    float v  = fmaf(di, acc, di * di * g_h[(size_t)i * NH + f]) + b1[f];
    g_h1[(size_t)i * NH + f] = fmaxf(v, 0.f);
}

// ------------------- GEMM2: g_g = h1[NN,256] @ W2[256,7] --------------------
__global__ void gemm2_kernel(const float* __restrict__ W2) {
    __shared__ float sW[NH * NC];
    const int tid = threadIdx.x;
    for (int t = tid; t < NH * NC; t += 256) sW[t] = W2[t];
    __syncthreads();
    const int lane = tid & 31;
    const int node = blockIdx.x * 8 + (tid >> 5);
    float p[NC];
    #pragma unroll
    for (int j = 0; j < NC; j++) p[j] = 0.f;
    #pragma unroll
    for (int u = 0; u < 8; u++) {
        int k = u * 32 + lane;
        float v = g_h1[(size_t)node * NH + k];
        #pragma unroll
        for (int j = 0; j < NC; j++) p[j] = fmaf(v, sW[k * NC + j], p[j]);
    }
    #pragma unroll
    for (int o = 16; o > 0; o >>= 1)
        #pragma unroll
        for (int j = 0; j < NC; j++) p[j] += __shfl_down_sync(0xffffffffu, p[j], o);
    if (lane == 0) {
        #pragma unroll
        for (int j = 0; j < NC; j++) g_g[node * 8 + j] = p[j];
        g_g[node * 8 + 7] = 0.f;
    }
}

// ------------------- aggregation layer 2 (7-wide, CSR gather) ---------------
__global__ void agg2_kernel(const float* __restrict__ b2, float* __restrict__ out) {
    const int tid  = threadIdx.x;            // 32 nodes x 8 threads
    const int node = blockIdx.x * 32 + (tid >> 3);
    const int j    = tid & 7;
    if (node >= NN) return;
    const int start = g_rowptr[node], end = g_rowptr[node + 1];
    float acc = 0.f;
    for (int p = start; p < end; p++) {
        int s = g_col[p];
        acc = fmaf(g_dinv[s], g_g[s * 8 + j], acc);
    }
    float di = g_dinv[node];
    float v  = fmaf(di, acc, di * di * g_g[node * 8 + j]);
    if (j < NC) out[node * NC + j] = v + b2[j];
}

// ------------------- launch --------------------------------------------------
extern "C" void kernel_launch(void* const* d_in, const int* in_sizes, int n_in,
                              void* d_out, int out_size) {
    const float* x    = (const float*)d_in[0];
    const int*   ei32 = (const int*)d_in[1];   // int32 OR int64 (auto-detected)
    const float* W1   = (const float*)d_in[2];
    const float* b1   = (const float*)d_in[3];
    const float* W2   = (const float*)d_in[4];
    const float* b2   = (const float*)d_in[5];
    float*       out  = (float*)d_out;

    detect_kernel<<<1, 32>>>(ei32);
    zero_cnt_kernel<<<(NN + 255) / 256, 256>>>();
    count_kernel<<<(NE + 255) / 256, 256>>>(ei32);
    scan_kernel<<<1, 1024>>>();
    fill_kernel<<<(NE + 255) / 256, 256>>>(ei32);

    dim3 g1(2, (NN + 127) / 128);   // (n-tiles, m-tiles)
    mma_gemm1_kernel<<<g1, 256>>>(x, W1);

    agg1_kernel<<<NN, 256>>>(b1);
    gemm2_kernel<<<NN / 8, 256>>>(W2);
    agg2_kernel<<<(NN + 31) / 32, 256>>>(b2, out);
}

// round 13
// speedup vs baseline: 1.5514x; 1.4611x over previous
#include <cuda_runtime.h>
#include <cuda_bf16.h>
#include <cstdint>

#define NN 50000
#define NE 1600000
#define NF 1433
#define NH 256
#define NC 7
#define NT_K 90                  // ceil(NF/16)
#define SCAN_NB 196              // 196*256 = 50176 >= NN

// ------------------- scratch (static device globals; no runtime alloc) ----
__device__ int   g_cnt[NN];
__device__ int   g_rowptr[NN + 1];
__device__ int   g_cur[NN];
__device__ float g_dinv[NN];
__device__ int   g_col[NE];
__device__ int   g_is64;
__device__ int   g_part[SCAN_NB];
__device__ float g_h [(size_t)NN * NH];   // x @ W1
__device__ float g_h1[(size_t)NN * NH];   // relu(agg1 + b1)
__device__ float g_g [NN * 8];            // h1 @ W2, padded stride 8

// ------------------- mma/ldmatrix helpers (sm_80 baseline ISA) -------------
__device__ __forceinline__ uint32_t smem_u32(const void* p) {
    uint32_t a;
    asm("{ .reg .u64 t; cvta.to.shared.u64 t, %1; cvt.u32.u64 %0, t; }"
        : "=r"(a) : "l"(p));
    return a;
}
__device__ __forceinline__ void ldsm_x4(uint32_t* r, uint32_t a) {
    asm volatile("ldmatrix.sync.aligned.m8n8.x4.shared.b16 {%0,%1,%2,%3}, [%4];"
                 : "=r"(r[0]), "=r"(r[1]), "=r"(r[2]), "=r"(r[3]) : "r"(a));
}
__device__ __forceinline__ void ldsm_x4_t(uint32_t* r, uint32_t a) {
    asm volatile("ldmatrix.sync.aligned.m8n8.x4.trans.shared.b16 {%0,%1,%2,%3}, [%4];"
                 : "=r"(r[0]), "=r"(r[1]), "=r"(r[2]), "=r"(r[3]) : "r"(a));
}
__device__ __forceinline__ void mma16816(float* d, const uint32_t* a, const uint32_t* b) {
    asm volatile("mma.sync.aligned.m16n8k16.row.col.f32.bf16.bf16.f32 "
                 "{%0,%1,%2,%3}, {%4,%5,%6,%7}, {%8,%9}, {%0,%1,%2,%3};"
                 : "+f"(d[0]), "+f"(d[1]), "+f"(d[2]), "+f"(d[3])
                 : "r"(a[0]), "r"(a[1]), "r"(a[2]), "r"(a[3]), "r"(b[0]), "r"(b[1]));
}

// ------------------- dtype detection ---------------------------------------
__global__ void detect_kernel(const int* __restrict__ ei32) {
    if (threadIdx.x == 0 && blockIdx.x == 0) {
        int flag = 1;
        for (int i = 1; i < 200; i += 2)
            if (ei32[i] != 0) { flag = 0; break; }
        g_is64 = flag;
    }
}
__device__ __forceinline__ int edge_src(const int* ei32, int e) {
    return g_is64 ? ei32[2 * (size_t)e] : ei32[e];
}
__device__ __forceinline__ int edge_dst(const int* ei32, int e) {
    return g_is64 ? ei32[2 * ((size_t)NE + e)] : ei32[NE + e];
}

// ------------------- graph preprocessing ------------------------------------
__global__ void zero_cnt_kernel() {
    int i = blockIdx.x * blockDim.x + threadIdx.x;
    if (i < NN) g_cnt[i] = 0;
}
__global__ void count_kernel(const int* __restrict__ ei32) {
    int e = blockIdx.x * blockDim.x + threadIdx.x;
    if (e < NE) {
        int d = edge_dst(ei32, e);
        if ((unsigned)d < NN) atomicAdd(&g_cnt[d], 1);
    }
}

// ---- parallel scan: A) block sums, B) scan partials, C) per-block prefix ---
__device__ __forceinline__ int block_excl_scan_256(int v, int tid, int* warp_sums,
                                                   int* total_out) {
    const int lane = tid & 31, wid = tid >> 5;
    int x = v;
    #pragma unroll
    for (int o = 1; o < 32; o <<= 1) {
        int t = __shfl_up_sync(0xffffffffu, x, o);
        if (lane >= o) x += t;
    }
    if (lane == 31) warp_sums[wid] = x;
    __syncthreads();
    if (tid < 8) {
        int y = warp_sums[tid];
        #pragma unroll
        for (int o = 1; o < 8; o <<= 1) {
            int t = __shfl_up_sync(0xffu, y, o);
            if (tid >= o) y += t;
        }
        warp_sums[tid] = y;
    }
    __syncthreads();
    int excl = x - v + (wid ? warp_sums[wid - 1] : 0);
    *total_out = warp_sums[7];
    return excl;
}

__global__ void scanA_kernel() {       // 196 blocks x 256: per-block sums
    __shared__ int warp_sums[8];
    const int tid = threadIdx.x;
    int i = blockIdx.x * 256 + tid;
    int v = (i < NN) ? g_cnt[i] : 0;
    int lane = tid & 31, wid = tid >> 5;
    int x = v;
    #pragma unroll
    for (int o = 1; o < 32; o <<= 1) x += __shfl_down_sync(0xffffffffu, x, o);
    if (lane == 0) warp_sums[wid] = x;
    __syncthreads();
    if (tid == 0) {
        int s = 0;
        #pragma unroll
        for (int w = 0; w < 8; w++) s += warp_sums[w];
        g_part[blockIdx.x] = s;
    }
}
__global__ void scanB_kernel() {       // 1 block x 256: exclusive scan partials
    __shared__ int warp_sums[8];
    const int tid = threadIdx.x;
    int v = (tid < SCAN_NB) ? g_part[tid] : 0;
    int total;
    int excl = block_excl_scan_256(v, tid, warp_sums, &total);
    if (tid < SCAN_NB) g_part[tid] = excl;
    if (tid == 0) g_rowptr[NN] = total;
}
__global__ void scanC_kernel() {       // 196 blocks x 256: write prefixes
    __shared__ int warp_sums[8];
    const int tid = threadIdx.x;
    int i = blockIdx.x * 256 + tid;
    int v = (i < NN) ? g_cnt[i] : 0;
    int total;
    int excl = block_excl_scan_256(v, tid, warp_sums, &total) + g_part[blockIdx.x];
    if (i < NN) {
        g_rowptr[i] = excl;
        g_cur[i]    = excl;
        g_dinv[i]   = rsqrtf((float)(v + 1));   // +1 = self loop
    }
}

__global__ void fill_kernel(const int* __restrict__ ei32) {
    int e = blockIdx.x * blockDim.x + threadIdx.x;
    if (e < NE) {
        int s = edge_src(ei32, e);
        int d = edge_dst(ei32, e);
        if ((unsigned)s < NN && (unsigned)d < NN) {
            int p = atomicAdd(&g_cur[d], 1);
            if ((unsigned)p < NE) g_col[p] = s;
        }
    }
}

// ------------------- GEMM1: g_h = x @ W1 via HMMA bf16 3-pass ---------------
// CTA tile 128x128, 8 warps (warp = 32m x 64n), K-step 16, double-buffered.
#define ST_AH 0
#define ST_AL 6144
#define ST_BH 12288
#define ST_BL 16640
#define ST_SZ 20992

__global__ void __launch_bounds__(256) mma_gemm1_kernel(const float* __restrict__ A,
                                                        const float* __restrict__ B) {
    __shared__ __align__(16) char smem[2 * ST_SZ];
    const uint32_t sb = smem_u32(smem);
    const int tid  = threadIdx.x;
    const int lane = tid & 31, wid = tid >> 5;
    const int row0 = blockIdx.y * 128;
    const int col0 = blockIdx.x * 128;
    const int wm = wid & 3;
    const int wn = wid >> 2;

    float acc[2][8][4];
    #pragma unroll
    for (int i = 0; i < 2; i++)
        #pragma unroll
        for (int j = 0; j < 8; j++)
            #pragma unroll
            for (int r = 0; r < 4; r++) acc[i][j][r] = 0.f;

    const int a_r0 = tid >> 2, a_c = tid & 3;
    const int b_kk = tid >> 4, b_nn = (tid & 15) * 8;

    float av[2][4];
    float bv[8];

    // ---- prologue: stage 0 direct --------------------------------------
    {
        #pragma unroll
        for (int q = 0; q < 2; q++) {
            int r = a_r0 + q * 64;
            int row = row0 + r;
            #pragma unroll
            for (int j = 0; j < 4; j++) {
                int k = a_c * 4 + j;
                av[q][j] = (row < NN && k < NF) ? A[(size_t)row * NF + k] : 0.f;
            }
        }
        if (b_kk < NF) {
            float4 v0 = *(const float4*)&B[(size_t)b_kk * NH + col0 + b_nn];
            float4 v1 = *(const float4*)&B[(size_t)b_kk * NH + col0 + b_nn + 4];
            bv[0]=v0.x; bv[1]=v0.y; bv[2]=v0.z; bv[3]=v0.w;
            bv[4]=v1.x; bv[5]=v1.y; bv[6]=v1.z; bv[7]=v1.w;
        } else {
            #pragma unroll
            for (int j = 0; j < 8; j++) bv[j] = 0.f;
        }
        char* st = smem;
        #pragma unroll
        for (int q = 0; q < 2; q++) {
            int r = a_r0 + q * 64;
            __nv_bfloat16 h[4], l[4];
            #pragma unroll
            for (int j = 0; j < 4; j++) {
                h[j] = __float2bfloat16(av[q][j]);
                l[j] = __float2bfloat16(av[q][j] - __bfloat162float(h[j]));
            }
            *(uint2*)(st + ST_AH + r * 48 + a_c * 8) = *(uint2*)h;
            *(uint2*)(st + ST_AL + r * 48 + a_c * 8) = *(uint2*)l;
        }
        {
            __nv_bfloat16 h[8], l[8];
            #pragma unroll
            for (int j = 0; j < 8; j++) {
                h[j] = __float2bfloat16(bv[j]);
                l[j] = __float2bfloat16(bv[j] - __bfloat162float(h[j]));
            }
            *(uint4*)(st + ST_BH + b_kk * 272 + b_nn * 2) = *(uint4*)h;
            *(uint4*)(st + ST_BL + b_kk * 272 + b_nn * 2) = *(uint4*)l;
        }
    }
    __syncthreads();

    const uint32_t a_lrow = (lane & 15);
    const uint32_t a_lcb  = (uint32_t)(lane >> 4) << 4;
    const uint32_t b_lk   = (lane & 7) + ((lane & 8) ? 8 : 0);
    const uint32_t b_ln   = (lane & 16) ? 8 : 0;

    for (int t = 0; t < NT_K; t++) {
        const int buf = t & 1;
        const bool more = (t + 1 < NT_K);

        if (more) {
            int k0 = (t + 1) * 16;
            #pragma unroll
            for (int q = 0; q < 2; q++) {
                int r = a_r0 + q * 64;
                int row = row0 + r;
                #pragma unroll
                for (int j = 0; j < 4; j++) {
                    int k = k0 + a_c * 4 + j;
                    av[q][j] = (row < NN && k < NF) ? A[(size_t)row * NF + k] : 0.f;
                }
            }
            int k = k0 + b_kk;
            if (k < NF) {
                float4 v0 = *(const float4*)&B[(size_t)k * NH + col0 + b_nn];
                float4 v1 = *(const float4*)&B[(size_t)k * NH + col0 + b_nn + 4];
                bv[0]=v0.x; bv[1]=v0.y; bv[2]=v0.z; bv[3]=v0.w;
                bv[4]=v1.x; bv[5]=v1.y; bv[6]=v1.z; bv[7]=v1.w;
            } else {
                #pragma unroll
                for (int j = 0; j < 8; j++) bv[j] = 0.f;
            }
        }

        const uint32_t base = sb + (uint32_t)buf * ST_SZ;
        #pragma unroll
        for (int term = 0; term < 3; term++) {
            const uint32_t Aoff = (term == 2) ? ST_AL : ST_AH;
            const uint32_t Boff = (term == 1) ? ST_BL : ST_BH;
            uint32_t a0[4], a1[4];
            uint32_t aaddr = base + Aoff + (wm * 32 + a_lrow) * 48 + a_lcb;
            ldsm_x4(a0, aaddr);
            ldsm_x4(a1, aaddr + 16 * 48);
            #pragma unroll
            for (int jj = 0; jj < 4; jj++) {
                uint32_t b[4];
                uint32_t baddr = base + Boff + b_lk * 272 +
                                 (uint32_t)(wn * 64 + jj * 16 + b_ln) * 2;
                ldsm_x4_t(b, baddr);
                mma16816(acc[0][2 * jj],     a0, b);
                mma16816(acc[0][2 * jj + 1], a0, b + 2);
                mma16816(acc[1][2 * jj],     a1, b);
                mma16816(acc[1][2 * jj + 1], a1, b + 2);
            }
        }

        if (more) {
            char* st = smem + (buf ^ 1) * ST_SZ;
            #pragma unroll
            for (int q = 0; q < 2; q++) {
                int r = a_r0 + q * 64;
                __nv_bfloat16 h[4], l[4];
                #pragma unroll
                for (int j = 0; j < 4; j++) {
                    h[j] = __float2bfloat16(av[q][j]);
                    l[j] = __float2bfloat16(av[q][j] - __bfloat162float(h[j]));
                }
                *(uint2*)(st + ST_AH + r * 48 + a_c * 8) = *(uint2*)h;
                *(uint2*)(st + ST_AL + r * 48 + a_c * 8) = *(uint2*)l;
            }
            {
                __nv_bfloat16 h[8], l[8];
                #pragma unroll
                for (int j = 0; j < 8; j++) {
                    h[j] = __float2bfloat16(bv[j]);
                    l[j] = __float2bfloat16(bv[j] - __bfloat162float(h[j]));
                }
                *(uint4*)(st + ST_BH + b_kk * 272 + b_nn * 2) = *(uint4*)h;
                *(uint4*)(st + ST_BL + b_kk * 272 + b_nn * 2) = *(uint4*)l;
            }
        }
        __syncthreads();
    }

    #pragma unroll
    for (int i = 0; i < 2; i++) {
        int row = row0 + wm * 32 + i * 16 + (lane >> 2);
        #pragma unroll
        for (int j = 0; j < 8; j++) {
            int colb = col0 + wn * 64 + j * 8 + (lane & 3) * 2;
            if (row < NN)
                *(float2*)&g_h[(size_t)row * NH + colb] =
                    make_float2(acc[i][j][0], acc[i][j][1]);
            if (row + 8 < NN)
                *(float2*)&g_h[(size_t)(row + 8) * NH + colb] =
                    make_float2(acc[i][j][2], acc[i][j][3]);
        }
    }
}

// ------------------- aggregation layer 1 (CSR gather, no atomics) -----------
__global__ void agg1_kernel(const float* __restrict__ b1) {
    __shared__ int   scol[128];
    __shared__ float snrm[128];
    const int i = blockIdx.x;
    const int f = threadIdx.x;   // 256 = NH
    const int start = g_rowptr[i];
    const int end   = g_rowptr[i + 1];
    float acc = 0.f;
    for (int p0 = start; p0 < end; p0 += 128) {
        int n = min(128, end - p0);
        if (f < n) {
            int s = g_col[p0 + f];
            scol[f] = s;
            snrm[f] = g_dinv[s];
        }
        __syncthreads();
        int j = 0;
        for (; j + 4 <= n; j += 4) {
            int s0 = scol[j], s1 = scol[j + 1], s2 = scol[j + 2], s3 = scol[j + 3];
            float w0 = snrm[j], w1 = snrm[j + 1], w2 = snrm[j + 2], w3 = snrm[j + 3];
            float h0  = g_h[(size_t)s0 * NH + f];
            float h1v = g_h[(size_t)s1 * NH + f];
            float h2  = g_h[(size_t)s2 * NH + f];
            float h3  = g_h[(size_t)s3 * NH + f];
            acc = fmaf(w0, h0, acc);
            acc = fmaf(w1, h1v, acc);
            acc = fmaf(w2, h2, acc);
            acc = fmaf(w3, h3, acc);
        }
        for (; j < n; j++)
            acc = fmaf(snrm[j], g_h[(size_t)scol[j] * NH + f], acc);
        __syncthreads();
    }
    float di = g_dinv[i];
    float v  = fmaf(di, acc, di * di * g_h[(size_t)i * NH + f]) + b1[f];
    g_h1[(size_t)i * NH + f] = fmaxf(v, 0.f);
}

// ------------------- GEMM2: g_g = h1[NN,256] @ W2[256,7] --------------------
__global__ void gemm2_kernel(const float* __restrict__ W2) {
    __shared__ float sW[NH * NC];
    const int tid = threadIdx.x;
    for (int t = tid; t < NH * NC; t += 256) sW[t] = W2[t];
    __syncthreads();
    const int lane = tid & 31;
    const int node = blockIdx.x * 8 + (tid >> 5);
    float p[NC];
    #pragma unroll
    for (int j = 0; j < NC; j++) p[j] = 0.f;
    #pragma unroll
    for (int u = 0; u < 8; u++) {
        int k = u * 32 + lane;
        float v = g_h1[(size_t)node * NH + k];
        #pragma unroll
        for (int j = 0; j < NC; j++) p[j] = fmaf(v, sW[k * NC + j], p[j]);
    }
    #pragma unroll
    for (int o = 16; o > 0; o >>= 1)
        #pragma unroll
        for (int j = 0; j < NC; j++) p[j] += __shfl_down_sync(0xffffffffu, p[j], o);
    if (lane == 0) {
        #pragma unroll
        for (int j = 0; j < NC; j++) g_g[node * 8 + j] = p[j];
        g_g[node * 8 + 7] = 0.f;
    }
}

// ------------------- aggregation layer 2 (7-wide, CSR gather) ---------------
__global__ void agg2_kernel(const float* __restrict__ b2, float* __restrict__ out) {
    const int tid  = threadIdx.x;
    const int node = blockIdx.x * 32 + (tid >> 3);
    const int j    = tid & 7;
    if (node >= NN) return;
    const int start = g_rowptr[node], end = g_rowptr[node + 1];
    float acc = 0.f;
    for (int p = start; p < end; p++) {
        int s = g_col[p];
        acc = fmaf(g_dinv[s], g_g[s * 8 + j], acc);
    }
    float di = g_dinv[node];
    float v  = fmaf(di, acc, di * di * g_g[node * 8 + j]);
    if (j < NC) out[node * NC + j] = v + b2[j];
}

// ------------------- launch --------------------------------------------------
extern "C" void kernel_launch(void* const* d_in, const int* in_sizes, int n_in,
                              void* d_out, int out_size) {
    const float* x    = (const float*)d_in[0];
    const int*   ei32 = (const int*)d_in[1];   // int32 OR int64 (auto-detected)
    const float* W1   = (const float*)d_in[2];
    const float* b1   = (const float*)d_in[3];
    const float* W2   = (const float*)d_in[4];
    const float* b2   = (const float*)d_in[5];
    float*       out  = (float*)d_out;

    detect_kernel<<<1, 32>>>(ei32);
    zero_cnt_kernel<<<(NN + 255) / 256, 256>>>();
    count_kernel<<<(NE + 255) / 256, 256>>>(ei32);

    // gemm1 is independent of graph preprocessing; placed 4th so the ncu
    // capture window (-s 5 -c 1, ~2 harness launches ahead of ours) lands on it.
    dim3 g1(2, (NN + 127) / 128);   // (n-tiles, m-tiles)
    mma_gemm1_kernel<<<g1, 256>>>(x, W1);

    scanA_kernel<<<SCAN_NB, 256>>>();
    scanB_kernel<<<1, 256>>>();
    scanC_kernel<<<SCAN_NB, 256>>>();
    fill_kernel<<<(NE + 255) / 256, 256>>>(ei32);

    agg1_kernel<<<NN, 256>>>(b1);
    gemm2_kernel<<<NN / 8, 256>>>(W2);
    agg2_kernel<<<(NN + 31) / 32, 256>>>(b2, out);
}

// round 14
// speedup vs baseline: 1.9719x; 1.2711x over previous
#include <cuda_runtime.h>
#include <cuda_bf16.h>
#include <cstdint>

#define NN 50000
#define NE 1600000
#define NF 1433
#define NH 256
#define NC 7
#define NT_K 90                  // ceil(NF/16)
#define SCAN_NB 196              // 196*256 = 50176 >= NN

// ------------------- scratch (static device globals; no runtime alloc) ----
__device__ int   g_cnt[NN];
__device__ int   g_rowptr[NN + 1];
__device__ int   g_cur[NN];
__device__ float g_dinv[NN];
__device__ int   g_col[NE];
__device__ int   g_is64;
__device__ int   g_part[SCAN_NB];
__device__ float g_h [(size_t)NN * NH];   // x @ W1
__device__ float g_h1[(size_t)NN * NH];   // relu(agg1 + b1)
__device__ float g_g [NN * 8];            // h1 @ W2, padded stride 8

// ------------------- mma/ldmatrix helpers (sm_80 baseline ISA) -------------
__device__ __forceinline__ uint32_t smem_u32(const void* p) {
    uint32_t a;
    asm("{ .reg .u64 t; cvta.to.shared.u64 t, %1; cvt.u32.u64 %0, t; }"
        : "=r"(a) : "l"(p));
    return a;
}
__device__ __forceinline__ void ldsm_x4(uint32_t* r, uint32_t a) {
    asm volatile("ldmatrix.sync.aligned.m8n8.x4.shared.b16 {%0,%1,%2,%3}, [%4];"
                 : "=r"(r[0]), "=r"(r[1]), "=r"(r[2]), "=r"(r[3]) : "r"(a));
}
__device__ __forceinline__ void ldsm_x4_t(uint32_t* r, uint32_t a) {
    asm volatile("ldmatrix.sync.aligned.m8n8.x4.trans.shared.b16 {%0,%1,%2,%3}, [%4];"
                 : "=r"(r[0]), "=r"(r[1]), "=r"(r[2]), "=r"(r[3]) : "r"(a));
}
__device__ __forceinline__ void mma16816(float* d, const uint32_t* a, const uint32_t* b) {
    asm volatile("mma.sync.aligned.m16n8k16.row.col.f32.bf16.bf16.f32 "
                 "{%0,%1,%2,%3}, {%4,%5,%6,%7}, {%8,%9}, {%0,%1,%2,%3};"
                 : "+f"(d[0]), "+f"(d[1]), "+f"(d[2]), "+f"(d[3])
                 : "r"(a[0]), "r"(a[1]), "r"(a[2]), "r"(a[3]), "r"(b[0]), "r"(b[1]));
}

// ------------------- dtype detection ---------------------------------------
__global__ void detect_kernel(const int* __restrict__ ei32) {
    if (threadIdx.x == 0 && blockIdx.x == 0) {
        int flag = 1;
        for (int i = 1; i < 200; i += 2)
            if (ei32[i] != 0) { flag = 0; break; }
        g_is64 = flag;
    }
}
__device__ __forceinline__ int edge_src(const int* ei32, int e) {
    return g_is64 ? ei32[2 * (size_t)e] : ei32[e];
}
__device__ __forceinline__ int edge_dst(const int* ei32, int e) {
    return g_is64 ? ei32[2 * ((size_t)NE + e)] : ei32[NE + e];
}

// ------------------- graph preprocessing ------------------------------------
__global__ void zero_cnt_kernel() {
    int i = blockIdx.x * blockDim.x + threadIdx.x;
    if (i < NN) g_cnt[i] = 0;
}
__global__ void count_kernel(const int* __restrict__ ei32) {
    int e = blockIdx.x * blockDim.x + threadIdx.x;
    if (e < NE) {
        int d = edge_dst(ei32, e);
        if ((unsigned)d < NN) atomicAdd(&g_cnt[d], 1);
    }
}

// ---- parallel scan: A) block sums, B) scan partials, C) per-block prefix ---
__device__ __forceinline__ int block_excl_scan_256(int v, int tid, int* warp_sums,
                                                   int* total_out) {
    const int lane = tid & 31, wid = tid >> 5;
    int x = v;
    #pragma unroll
    for (int o = 1; o < 32; o <<= 1) {
        int t = __shfl_up_sync(0xffffffffu, x, o);
        if (lane >= o) x += t;
    }
    if (lane == 31) warp_sums[wid] = x;
    __syncthreads();
    if (tid < 8) {
        int y = warp_sums[tid];
        #pragma unroll
        for (int o = 1; o < 8; o <<= 1) {
            int t = __shfl_up_sync(0xffu, y, o);
            if (tid >= o) y += t;
        }
        warp_sums[tid] = y;
    }
    __syncthreads();
    int excl = x - v + (wid ? warp_sums[wid - 1] : 0);
    *total_out = warp_sums[7];
    return excl;
}

__global__ void scanA_kernel() {       // 196 blocks x 256: per-block sums
    __shared__ int warp_sums[8];
    const int tid = threadIdx.x;
    int i = blockIdx.x * 256 + tid;
    int v = (i < NN) ? g_cnt[i] : 0;
    int lane = tid & 31, wid = tid >> 5;
    int x = v;
    #pragma unroll
    for (int o = 1; o < 32; o <<= 1) x += __shfl_down_sync(0xffffffffu, x, o);
    if (lane == 0) warp_sums[wid] = x;
    __syncthreads();
    if (tid == 0) {
        int s = 0;
        #pragma unroll
        for (int w = 0; w < 8; w++) s += warp_sums[w];
        g_part[blockIdx.x] = s;
    }
}
__global__ void scanB_kernel() {       // 1 block x 256: exclusive scan partials
    __shared__ int warp_sums[8];
    const int tid = threadIdx.x;
    int v = (tid < SCAN_NB) ? g_part[tid] : 0;
    int total;
    int excl = block_excl_scan_256(v, tid, warp_sums, &total);
    if (tid < SCAN_NB) g_part[tid] = excl;
    if (tid == 0) g_rowptr[NN] = total;
}
__global__ void scanC_kernel() {       // 196 blocks x 256: write prefixes
    __shared__ int warp_sums[8];
    const int tid = threadIdx.x;
    int i = blockIdx.x * 256 + tid;
    int v = (i < NN) ? g_cnt[i] : 0;
    int total;
    int excl = block_excl_scan_256(v, tid, warp_sums, &total) + g_part[blockIdx.x];
    if (i < NN) {
        g_rowptr[i] = excl;
        g_cur[i]    = excl;
        g_dinv[i]   = rsqrtf((float)(v + 1));   // +1 = self loop
    }
}

__global__ void fill_kernel(const int* __restrict__ ei32) {
    int e = blockIdx.x * blockDim.x + threadIdx.x;
    if (e < NE) {
        int s = edge_src(ei32, e);
        int d = edge_dst(ei32, e);
        if ((unsigned)s < NN && (unsigned)d < NN) {
            int p = atomicAdd(&g_cur[d], 1);
            if ((unsigned)p < NE) g_col[p] = s;
        }
    }
}

// ------------------- GEMM1: g_h = x @ W1 via HMMA bf16 3-pass ---------------
// CTA tile 128x128, 8 warps (warp = 32m x 64n), K-step 16, double-buffered.
// __launch_bounds__(256, 2): force regs<=128 so 2 CTAs co-reside per SM
// (R13 profile: regs=130 -> occ 12.5%, tensor pipe 33.6% -- occupancy-starved).
#define ST_AH 0
#define ST_AL 6144
#define ST_BH 12288
#define ST_BL 16640
#define ST_SZ 20992

__global__ void __launch_bounds__(256, 2) mma_gemm1_kernel(const float* __restrict__ A,
                                                           const float* __restrict__ B) {
    __shared__ __align__(16) char smem[2 * ST_SZ];
    const uint32_t sb = smem_u32(smem);
    const int tid  = threadIdx.x;
    const int lane = tid & 31, wid = tid >> 5;
    const int row0 = blockIdx.y * 128;
    const int col0 = blockIdx.x * 128;
    const int wm = wid & 3;
    const int wn = wid >> 2;

    float acc[2][8][4];
    #pragma unroll
    for (int i = 0; i < 2; i++)
        #pragma unroll
        for (int j = 0; j < 8; j++)
            #pragma unroll
            for (int r = 0; r < 4; r++) acc[i][j][r] = 0.f;

    const int a_r0 = tid >> 2, a_c = tid & 3;
    const int b_kk = tid >> 4, b_nn = (tid & 15) * 8;

    float av[2][4];
    float bv[8];

    // ---- prologue: stage 0 direct --------------------------------------
    {
        #pragma unroll
        for (int q = 0; q < 2; q++) {
            int r = a_r0 + q * 64;
            int row = row0 + r;
            #pragma unroll
            for (int j = 0; j < 4; j++) {
                int k = a_c * 4 + j;
                av[q][j] = (row < NN && k < NF) ? A[(size_t)row * NF + k] : 0.f;
            }
        }
        if (b_kk < NF) {
            float4 v0 = *(const float4*)&B[(size_t)b_kk * NH + col0 + b_nn];
            float4 v1 = *(const float4*)&B[(size_t)b_kk * NH + col0 + b_nn + 4];
            bv[0]=v0.x; bv[1]=v0.y; bv[2]=v0.z; bv[3]=v0.w;
            bv[4]=v1.x; bv[5]=v1.y; bv[6]=v1.z; bv[7]=v1.w;
        } else {
            #pragma unroll
            for (int j = 0; j < 8; j++) bv[j] = 0.f;
        }
        char* st = smem;
        #pragma unroll
        for (int q = 0; q < 2; q++) {
            int r = a_r0 + q * 64;
            __nv_bfloat16 h[4], l[4];
            #pragma unroll
            for (int j = 0; j < 4; j++) {
                h[j] = __float2bfloat16(av[q][j]);
                l[j] = __float2bfloat16(av[q][j] - __bfloat162float(h[j]));
            }
            *(uint2*)(st + ST_AH + r * 48 + a_c * 8) = *(uint2*)h;
            *(uint2*)(st + ST_AL + r * 48 + a_c * 8) = *(uint2*)l;
        }
        {
            __nv_bfloat16 h[8], l[8];
            #pragma unroll
            for (int j = 0; j < 8; j++) {
                h[j] = __float2bfloat16(bv[j]);
                l[j] = __float2bfloat16(bv[j] - __bfloat162float(h[j]));
            }
            *(uint4*)(st + ST_BH + b_kk * 272 + b_nn * 2) = *(uint4*)h;
            *(uint4*)(st + ST_BL + b_kk * 272 + b_nn * 2) = *(uint4*)l;
        }
    }
    __syncthreads();

    const uint32_t a_lrow = (lane & 15);
    const uint32_t a_lcb  = (uint32_t)(lane >> 4) << 4;
    const uint32_t b_lk   = (lane & 7) + ((lane & 8) ? 8 : 0);
    const uint32_t b_ln   = (lane & 16) ? 8 : 0;

    for (int t = 0; t < NT_K; t++) {
        const int buf = t & 1;
        const bool more = (t + 1 < NT_K);

        if (more) {
            int k0 = (t + 1) * 16;
            #pragma unroll
            for (int q = 0; q < 2; q++) {
                int r = a_r0 + q * 64;
                int row = row0 + r;
                #pragma unroll
                for (int j = 0; j < 4; j++) {
                    int k = k0 + a_c * 4 + j;
                    av[q][j] = (row < NN && k < NF) ? A[(size_t)row * NF + k] : 0.f;
                }
            }
            int k = k0 + b_kk;
            if (k < NF) {
                float4 v0 = *(const float4*)&B[(size_t)k * NH + col0 + b_nn];
                float4 v1 = *(const float4*)&B[(size_t)k * NH + col0 + b_nn + 4];
                bv[0]=v0.x; bv[1]=v0.y; bv[2]=v0.z; bv[3]=v0.w;
                bv[4]=v1.x; bv[5]=v1.y; bv[6]=v1.z; bv[7]=v1.w;
            } else {
                #pragma unroll
                for (int j = 0; j < 8; j++) bv[j] = 0.f;
            }
        }

        const uint32_t base = sb + (uint32_t)buf * ST_SZ;
        #pragma unroll
        for (int term = 0; term < 3; term++) {
            const uint32_t Aoff = (term == 2) ? ST_AL : ST_AH;
            const uint32_t Boff = (term == 1) ? ST_BL : ST_BH;
            uint32_t a0[4], a1[4];
            uint32_t aaddr = base + Aoff + (wm * 32 + a_lrow) * 48 + a_lcb;
            ldsm_x4(a0, aaddr);
            ldsm_x4(a1, aaddr + 16 * 48);
            #pragma unroll
            for (int jj = 0; jj < 4; jj++) {
                uint32_t b[4];
                uint32_t baddr = base + Boff + b_lk * 272 +
                                 (uint32_t)(wn * 64 + jj * 16 + b_ln) * 2;
                ldsm_x4_t(b, baddr);
                mma16816(acc[0][2 * jj],     a0, b);
                mma16816(acc[0][2 * jj + 1], a0, b + 2);
                mma16816(acc[1][2 * jj],     a1, b);
                mma16816(acc[1][2 * jj + 1], a1, b + 2);
            }
        }

        if (more) {
            char* st = smem + (buf ^ 1) * ST_SZ;
            #pragma unroll
            for (int q = 0; q < 2; q++) {
                int r = a_r0 + q * 64;
                __nv_bfloat16 h[4], l[4];
                #pragma unroll
                for (int j = 0; j < 4; j++) {
                    h[j] = __float2bfloat16(av[q][j]);
                    l[j] = __float2bfloat16(av[q][j] - __bfloat162float(h[j]));
                }
                *(uint2*)(st + ST_AH + r * 48 + a_c * 8) = *(uint2*)h;
                *(uint2*)(st + ST_AL + r * 48 + a_c * 8) = *(uint2*)l;
            }
            {
                __nv_bfloat16 h[8], l[8];
                #pragma unroll
                for (int j = 0; j < 8; j++) {
                    h[j] = __float2bfloat16(bv[j]);
                    l[j] = __float2bfloat16(bv[j] - __bfloat162float(h[j]));
                }
                *(uint4*)(st + ST_BH + b_kk * 272 + b_nn * 2) = *(uint4*)h;
                *(uint4*)(st + ST_BL + b_kk * 272 + b_nn * 2) = *(uint4*)l;
            }
        }
        __syncthreads();
    }

    #pragma unroll
    for (int i = 0; i < 2; i++) {
        int row = row0 + wm * 32 + i * 16 + (lane >> 2);
        #pragma unroll
        for (int j = 0; j < 8; j++) {
            int colb = col0 + wn * 64 + j * 8 + (lane & 3) * 2;
            if (row < NN)
                *(float2*)&g_h[(size_t)row * NH + colb] =
                    make_float2(acc[i][j][0], acc[i][j][1]);
            if (row + 8 < NN)
                *(float2*)&g_h[(size_t)(row + 8) * NH + colb] =
                    make_float2(acc[i][j][2], acc[i][j][3]);
        }
    }
}

// ------------------- aggregation layer 1 (CSR gather, no atomics) -----------
__global__ void agg1_kernel(const float* __restrict__ b1) {
    __shared__ int   scol[128];
    __shared__ float snrm[128];
    const int i = blockIdx.x;
    const int f = threadIdx.x;   // 256 = NH
    const int start = g_rowptr[i];
    const int end   = g_rowptr[i + 1];
    float acc = 0.f;
    for (int p0 = start; p0 < end; p0 += 128) {
        int n = min(128, end - p0);
        if (f < n) {
            int s = g_col[p0 + f];
            scol[f] = s;
            snrm[f] = g_dinv[s];
        }
        __syncthreads();
        int j = 0;
        for (; j + 4 <= n; j += 4) {
            int s0 = scol[j], s1 = scol[j + 1], s2 = scol[j + 2], s3 = scol[j + 3];
            float w0 = snrm[j], w1 = snrm[j + 1], w2 = snrm[j + 2], w3 = snrm[j + 3];
            float h0  = g_h[(size_t)s0 * NH + f];
            float h1v = g_h[(size_t)s1 * NH + f];
            float h2  = g_h[(size_t)s2 * NH + f];
            float h3  = g_h[(size_t)s3 * NH + f];
            acc = fmaf(w0, h0, acc);
            acc = fmaf(w1, h1v, acc);
            acc = fmaf(w2, h2, acc);
            acc = fmaf(w3, h3, acc);
        }
        for (; j < n; j++)
            acc = fmaf(snrm[j], g_h[(size_t)scol[j] * NH + f], acc);
        __syncthreads();
    }
    float di = g_dinv[i];
    float v  = fmaf(di, acc, di * di * g_h[(size_t)i * NH + f]) + b1[f];
    g_h1[(size_t)i * NH + f] = fmaxf(v, 0.f);
}

// ------------------- GEMM2: g_g = h1[NN,256] @ W2[256,7] --------------------
__global__ void gemm2_kernel(const float* __restrict__ W2) {
    __shared__ float sW[NH * NC];
    const int tid = threadIdx.x;
    for (int t = tid; t < NH * NC; t += 256) sW[t] = W2[t];
    __syncthreads();
    const int lane = tid & 31;
    const int node = blockIdx.x * 8 + (tid >> 5);
    float p[NC];
    #pragma unroll
    for (int j = 0; j < NC; j++) p[j] = 0.f;
    #pragma unroll
    for (int u = 0; u < 8; u++) {
        int k = u * 32 + lane;
        float v = g_h1[(size_t)node * NH + k];
        #pragma unroll
        for (int j = 0; j < NC; j++) p[j] = fmaf(v, sW[k * NC + j], p[j]);
    }
    #pragma unroll
    for (int o = 16; o > 0; o >>= 1)
        #pragma unroll
        for (int j = 0; j < NC; j++) p[j] += __shfl_down_sync(0xffffffffu, p[j], o);
    if (lane == 0) {
        #pragma unroll
        for (int j = 0; j < NC; j++) g_g[node * 8 + j] = p[j];
        g_g[node * 8 + 7] = 0.f;
    }
}

// ------------------- aggregation layer 2 (7-wide, CSR gather) ---------------
__global__ void agg2_kernel(const float* __restrict__ b2, float* __restrict__ out) {
    const int tid  = threadIdx.x;
    const int node = blockIdx.x * 32 + (tid >> 3);
    const int j    = tid & 7;
    if (node >= NN) return;
    const int start = g_rowptr[node], end = g_rowptr[node + 1];
    float acc = 0.f;
    for (int p = start; p < end; p++) {
        int s = g_col[p];
        acc = fmaf(g_dinv[s], g_g[s * 8 + j], acc);
    }
    float di = g_dinv[node];
    float v  = fmaf(di, acc, di * di * g_g[node * 8 + j]);
    if (j < NC) out[node * NC + j] = v + b2[j];
}

// ------------------- launch --------------------------------------------------
extern "C" void kernel_launch(void* const* d_in, const int* in_sizes, int n_in,
                              void* d_out, int out_size) {
    const float* x    = (const float*)d_in[0];
    const int*   ei32 = (const int*)d_in[1];   // int32 OR int64 (auto-detected)
    const float* W1   = (const float*)d_in[2];
    const float* b1   = (const float*)d_in[3];
    const float* W2   = (const float*)d_in[4];
    const float* b2   = (const float*)d_in[5];
    float*       out  = (float*)d_out;

    detect_kernel<<<1, 32>>>(ei32);
    zero_cnt_kernel<<<(NN + 255) / 256, 256>>>();
    count_kernel<<<(NE + 255) / 256, 256>>>(ei32);

    // gemm1 placed 4th so the ncu capture window (-s 5 -c 1) lands on it.
    dim3 g1(2, (NN + 127) / 128);   // (n-tiles, m-tiles)
    mma_gemm1_kernel<<<g1, 256>>>(x, W1);

    scanA_kernel<<<SCAN_NB, 256>>>();
    scanB_kernel<<<1, 256>>>();
    scanC_kernel<<<SCAN_NB, 256>>>();
    fill_kernel<<<(NE + 255) / 256, 256>>>(ei32);

    agg1_kernel<<<NN, 256>>>(b1);
    gemm2_kernel<<<NN / 8, 256>>>(W2);
    agg2_kernel<<<(NN + 31) / 32, 256>>>(b2, out);
}

// round 15
// speedup vs baseline: 1.9953x; 1.0118x over previous
#include <cuda_runtime.h>
#include <cuda_bf16.h>
#include <cstdint>

#define NN 50000
#define NE 1600000
#define NF 1433
#define NH 256
#define NC 7
#define NT_K 90                  // ceil(NF/16)
#define SCAN_NB 196              // 196*256 = 50176 >= NN

// ------------------- scratch (static device globals; no runtime alloc) ----
__device__ int   g_cnt[NN];
__device__ int   g_rowptr[NN + 1];
__device__ int   g_cur[NN];
__device__ float g_dinv[NN];
__device__ int   g_col[NE];
__device__ int   g_is64;
__device__ int   g_part[SCAN_NB];
__device__ float g_h [(size_t)NN * NH];   // x @ W1
__device__ float g_h1[(size_t)NN * NH];   // relu(agg1 + b1)
__device__ float g_g [NN * 8];            // h1 @ W2, padded stride 8

// ------------------- mma/ldmatrix helpers (sm_80 baseline ISA) -------------
__device__ __forceinline__ uint32_t smem_u32(const void* p) {
    uint32_t a;
    asm("{ .reg .u64 t; cvta.to.shared.u64 t, %1; cvt.u32.u64 %0, t; }"
        : "=r"(a) : "l"(p));
    return a;
}
__device__ __forceinline__ void ldsm_x4(uint32_t* r, uint32_t a) {
    asm volatile("ldmatrix.sync.aligned.m8n8.x4.shared.b16 {%0,%1,%2,%3}, [%4];"
                 : "=r"(r[0]), "=r"(r[1]), "=r"(r[2]), "=r"(r[3]) : "r"(a));
}
__device__ __forceinline__ void ldsm_x4_t(uint32_t* r, uint32_t a) {
    asm volatile("ldmatrix.sync.aligned.m8n8.x4.trans.shared.b16 {%0,%1,%2,%3}, [%4];"
                 : "=r"(r[0]), "=r"(r[1]), "=r"(r[2]), "=r"(r[3]) : "r"(a));
}
__device__ __forceinline__ void mma16816(float* d, const uint32_t* a, const uint32_t* b) {
    asm volatile("mma.sync.aligned.m16n8k16.row.col.f32.bf16.bf16.f32 "
                 "{%0,%1,%2,%3}, {%4,%5,%6,%7}, {%8,%9}, {%0,%1,%2,%3};"
                 : "+f"(d[0]), "+f"(d[1]), "+f"(d[2]), "+f"(d[3])
                 : "r"(a[0]), "r"(a[1]), "r"(a[2]), "r"(a[3]), "r"(b[0]), "r"(b[1]));
}

// ------------------- dtype detection ---------------------------------------
__global__ void detect_kernel(const int* __restrict__ ei32) {
    if (threadIdx.x == 0 && blockIdx.x == 0) {
        int flag = 1;
        for (int i = 1; i < 200; i += 2)
            if (ei32[i] != 0) { flag = 0; break; }
        g_is64 = flag;
    }
}
__device__ __forceinline__ int edge_src(const int* ei32, int e) {
    return g_is64 ? ei32[2 * (size_t)e] : ei32[e];
}
__device__ __forceinline__ int edge_dst(const int* ei32, int e) {
    return g_is64 ? ei32[2 * ((size_t)NE + e)] : ei32[NE + e];
}

// ------------------- graph preprocessing ------------------------------------
__global__ void zero_cnt_kernel() {
    int i = blockIdx.x * blockDim.x + threadIdx.x;
    if (i < NN) g_cnt[i] = 0;
}
__global__ void count_kernel(const int* __restrict__ ei32) {
    int e = blockIdx.x * blockDim.x + threadIdx.x;
    if (e < NE) {
        int d = edge_dst(ei32, e);
        if ((unsigned)d < NN) atomicAdd(&g_cnt[d], 1);
    }
}

// ---- parallel scan: A) block sums, B) scan partials, C) per-block prefix ---
__device__ __forceinline__ int block_excl_scan_256(int v, int tid, int* warp_sums,
                                                   int* total_out) {
    const int lane = tid & 31, wid = tid >> 5;
    int x = v;
    #pragma unroll
    for (int o = 1; o < 32; o <<= 1) {
        int t = __shfl_up_sync(0xffffffffu, x, o);
        if (lane >= o) x += t;
    }
    if (lane == 31) warp_sums[wid] = x;
    __syncthreads();
    if (tid < 8) {
        int y = warp_sums[tid];
        #pragma unroll
        for (int o = 1; o < 8; o <<= 1) {
            int t = __shfl_up_sync(0xffu, y, o);
            if (tid >= o) y += t;
        }
        warp_sums[tid] = y;
    }
    __syncthreads();
    int excl = x - v + (wid ? warp_sums[wid - 1] : 0);
    *total_out = warp_sums[7];
    return excl;
}

__global__ void scanA_kernel() {       // 196 blocks x 256: per-block sums
    __shared__ int warp_sums[8];
    const int tid = threadIdx.x;
    int i = blockIdx.x * 256 + tid;
    int v = (i < NN) ? g_cnt[i] : 0;
    int lane = tid & 31, wid = tid >> 5;
    int x = v;
    #pragma unroll
    for (int o = 1; o < 32; o <<= 1) x += __shfl_down_sync(0xffffffffu, x, o);
    if (lane == 0) warp_sums[wid] = x;
    __syncthreads();
    if (tid == 0) {
        int s = 0;
        #pragma unroll
        for (int w = 0; w < 8; w++) s += warp_sums[w];
        g_part[blockIdx.x] = s;
    }
}
__global__ void scanB_kernel() {       // 1 block x 256: exclusive scan partials
    __shared__ int warp_sums[8];
    const int tid = threadIdx.x;
    int v = (tid < SCAN_NB) ? g_part[tid] : 0;
    int total;
    int excl = block_excl_scan_256(v, tid, warp_sums, &total);
    if (tid < SCAN_NB) g_part[tid] = excl;
    if (tid == 0) g_rowptr[NN] = total;
}
__global__ void scanC_kernel() {       // 196 blocks x 256: write prefixes
    __shared__ int warp_sums[8];
    const int tid = threadIdx.x;
    int i = blockIdx.x * 256 + tid;
    int v = (i < NN) ? g_cnt[i] : 0;
    int total;
    int excl = block_excl_scan_256(v, tid, warp_sums, &total) + g_part[blockIdx.x];
    if (i < NN) {
        g_rowptr[i] = excl;
        g_cur[i]    = excl;
        g_dinv[i]   = rsqrtf((float)(v + 1));   // +1 = self loop
    }
}

__global__ void fill_kernel(const int* __restrict__ ei32) {
    int e = blockIdx.x * blockDim.x + threadIdx.x;
    if (e < NE) {
        int s = edge_src(ei32, e);
        int d = edge_dst(ei32, e);
        if ((unsigned)s < NN && (unsigned)d < NN) {
            int p = atomicAdd(&g_cur[d], 1);
            if ((unsigned)p < NE) g_col[p] = s;
        }
    }
}

// ------------------- GEMM1: g_h = x @ W1 via HMMA bf16 3-pass ---------------
// CTA tile 128x128, 8 warps (warp = 32m x 64n), K-step 16, double-buffered.
// R14 profile: L1=74.1% (LDSM-bound), tensor=50.1%. This version shares
// A and B fragments across the 3 split terms: 12 LDSM.x4/warp/k-step vs 18.
#define ST_AH 0
#define ST_AL 6144
#define ST_BH 12288
#define ST_BL 16640
#define ST_SZ 20992

__global__ void __launch_bounds__(256, 2) mma_gemm1_kernel(const float* __restrict__ A,
                                                           const float* __restrict__ B) {
    __shared__ __align__(16) char smem[2 * ST_SZ];
    const uint32_t sb = smem_u32(smem);
    const int tid  = threadIdx.x;
    const int lane = tid & 31, wid = tid >> 5;
    const int row0 = blockIdx.y * 128;
    const int col0 = blockIdx.x * 128;
    const int wm = wid & 3;
    const int wn = wid >> 2;

    float acc[2][8][4];
    #pragma unroll
    for (int i = 0; i < 2; i++)
        #pragma unroll
        for (int j = 0; j < 8; j++)
            #pragma unroll
            for (int r = 0; r < 4; r++) acc[i][j][r] = 0.f;

    const int a_r0 = tid >> 2, a_c = tid & 3;
    const int b_kk = tid >> 4, b_nn = (tid & 15) * 8;

    float av[2][4];
    float bv[8];

    // ---- prologue: stage 0 direct --------------------------------------
    {
        #pragma unroll
        for (int q = 0; q < 2; q++) {
            int r = a_r0 + q * 64;
            int row = row0 + r;
            #pragma unroll
            for (int j = 0; j < 4; j++) {
                int k = a_c * 4 + j;
                av[q][j] = (row < NN && k < NF) ? A[(size_t)row * NF + k] : 0.f;
            }
        }
        if (b_kk < NF) {
            float4 v0 = *(const float4*)&B[(size_t)b_kk * NH + col0 + b_nn];
            float4 v1 = *(const float4*)&B[(size_t)b_kk * NH + col0 + b_nn + 4];
            bv[0]=v0.x; bv[1]=v0.y; bv[2]=v0.z; bv[3]=v0.w;
            bv[4]=v1.x; bv[5]=v1.y; bv[6]=v1.z; bv[7]=v1.w;
        } else {
            #pragma unroll
            for (int j = 0; j < 8; j++) bv[j] = 0.f;
        }
        char* st = smem;
        #pragma unroll
        for (int q = 0; q < 2; q++) {
            int r = a_r0 + q * 64;
            __nv_bfloat16 h[4], l[4];
            #pragma unroll
            for (int j = 0; j < 4; j++) {
                h[j] = __float2bfloat16(av[q][j]);
                l[j] = __float2bfloat16(av[q][j] - __bfloat162float(h[j]));
            }
            *(uint2*)(st + ST_AH + r * 48 + a_c * 8) = *(uint2*)h;
            *(uint2*)(st + ST_AL + r * 48 + a_c * 8) = *(uint2*)l;
        }
        {
            __nv_bfloat16 h[8], l[8];
            #pragma unroll
            for (int j = 0; j < 8; j++) {
                h[j] = __float2bfloat16(bv[j]);
                l[j] = __float2bfloat16(bv[j] - __bfloat162float(h[j]));
            }
            *(uint4*)(st + ST_BH + b_kk * 272 + b_nn * 2) = *(uint4*)h;
            *(uint4*)(st + ST_BL + b_kk * 272 + b_nn * 2) = *(uint4*)l;
        }
    }
    __syncthreads();

    const uint32_t a_lrow = (lane & 15);
    const uint32_t a_lcb  = (uint32_t)(lane >> 4) << 4;
    const uint32_t b_lk   = (lane & 7) + ((lane & 8) ? 8 : 0);
    const uint32_t b_ln   = (lane & 16) ? 8 : 0;

    for (int t = 0; t < NT_K; t++) {
        const int buf = t & 1;
        const bool more = (t + 1 < NT_K);

        if (more) {
            int k0 = (t + 1) * 16;
            #pragma unroll
            for (int q = 0; q < 2; q++) {
                int r = a_r0 + q * 64;
                int row = row0 + r;
                #pragma unroll
                for (int j = 0; j < 4; j++) {
                    int k = k0 + a_c * 4 + j;
                    av[q][j] = (row < NN && k < NF) ? A[(size_t)row * NF + k] : 0.f;
                }
            }
            int k = k0 + b_kk;
            if (k < NF) {
                float4 v0 = *(const float4*)&B[(size_t)k * NH + col0 + b_nn];
                float4 v1 = *(const float4*)&B[(size_t)k * NH + col0 + b_nn + 4];
                bv[0]=v0.x; bv[1]=v0.y; bv[2]=v0.z; bv[3]=v0.w;
                bv[4]=v1.x; bv[5]=v1.y; bv[6]=v1.z; bv[7]=v1.w;
            } else {
                #pragma unroll
                for (int j = 0; j < 8; j++) bv[j] = 0.f;
            }
        }

        // ---- compute: fragment-shared 3-term accumulation -------------
        // acc += Ah*Bh + Al*Bh + Ah*Bl ; A frags loaded once, B frags once.
        {
            const uint32_t base = sb + (uint32_t)buf * ST_SZ;
            uint32_t ah0[4], ah1[4], al0[4], al1[4];
            const uint32_t arow = (uint32_t)(wm * 32 + a_lrow) * 48 + a_lcb;
            ldsm_x4(ah0, base + ST_AH + arow);
            ldsm_x4(ah1, base + ST_AH + arow + 16 * 48);
            ldsm_x4(al0, base + ST_AL + arow);
            ldsm_x4(al1, base + ST_AL + arow + 16 * 48);
            #pragma unroll
            for (int jj = 0; jj < 4; jj++) {
                const uint32_t boff = b_lk * 272 +
                                      (uint32_t)(wn * 64 + jj * 16 + b_ln) * 2;
                uint32_t bh[4];
                ldsm_x4_t(bh, base + ST_BH + boff);
                mma16816(acc[0][2 * jj],     ah0, bh);
                mma16816(acc[0][2 * jj + 1], ah0, bh + 2);
                mma16816(acc[1][2 * jj],     ah1, bh);
                mma16816(acc[1][2 * jj + 1], ah1, bh + 2);
                mma16816(acc[0][2 * jj],     al0, bh);
                mma16816(acc[0][2 * jj + 1], al0, bh + 2);
                mma16816(acc[1][2 * jj],     al1, bh);
                mma16816(acc[1][2 * jj + 1], al1, bh + 2);
                uint32_t bl[4];
                ldsm_x4_t(bl, base + ST_BL + boff);
                mma16816(acc[0][2 * jj],     ah0, bl);
                mma16816(acc[0][2 * jj + 1], ah0, bl + 2);
                mma16816(acc[1][2 * jj],     ah1, bl);
                mma16816(acc[1][2 * jj + 1], ah1, bl + 2);
            }
        }

        if (more) {
            char* st = smem + (buf ^ 1) * ST_SZ;
            #pragma unroll
            for (int q = 0; q < 2; q++) {
                int r = a_r0 + q * 64;
                __nv_bfloat16 h[4], l[4];
                #pragma unroll
                for (int j = 0; j < 4; j++) {
                    h[j] = __float2bfloat16(av[q][j]);
                    l[j] = __float2bfloat16(av[q][j] - __bfloat162float(h[j]));
                }
                *(uint2*)(st + ST_AH + r * 48 + a_c * 8) = *(uint2*)h;
                *(uint2*)(st + ST_AL + r * 48 + a_c * 8) = *(uint2*)l;
            }
            {
                __nv_bfloat16 h[8], l[8];
                #pragma unroll
                for (int j = 0; j < 8; j++) {
                    h[j] = __float2bfloat16(bv[j]);
                    l[j] = __float2bfloat16(bv[j] - __bfloat162float(h[j]));
                }
                *(uint4*)(st + ST_BH + b_kk * 272 + b_nn * 2) = *(uint4*)h;
                *(uint4*)(st + ST_BL + b_kk * 272 + b_nn * 2) = *(uint4*)l;
            }
        }
        __syncthreads();
    }

    #pragma unroll
    for (int i = 0; i < 2; i++) {
        int row = row0 + wm * 32 + i * 16 + (lane >> 2);
        #pragma unroll
        for (int j = 0; j < 8; j++) {
            int colb = col0 + wn * 64 + j * 8 + (lane & 3) * 2;
            if (row < NN)
                *(float2*)&g_h[(size_t)row * NH + colb] =
                    make_float2(acc[i][j][0], acc[i][j][1]);
            if (row + 8 < NN)
                *(float2*)&g_h[(size_t)(row + 8) * NH + colb] =
                    make_float2(acc[i][j][2], acc[i][j][3]);
        }
    }
}

// ------------------- aggregation layer 1 (CSR gather, no atomics) -----------
__global__ void agg1_kernel(const float* __restrict__ b1) {
    __shared__ int   scol[128];
    __shared__ float snrm[128];
    const int i = blockIdx.x;
    const int f = threadIdx.x;   // 256 = NH
    const int start = g_rowptr[i];
    const int end   = g_rowptr[i + 1];
    float acc = 0.f;
    for (int p0 = start; p0 < end; p0 += 128) {
        int n = min(128, end - p0);
        if (f < n) {
            int s = g_col[p0 + f];
            scol[f] = s;
            snrm[f] = g_dinv[s];
        }
        __syncthreads();
        int j = 0;
        for (; j + 4 <= n; j += 4) {
            int s0 = scol[j], s1 = scol[j + 1], s2 = scol[j + 2], s3 = scol[j + 3];
            float w0 = snrm[j], w1 = snrm[j + 1], w2 = snrm[j + 2], w3 = snrm[j + 3];
            float h0  = g_h[(size_t)s0 * NH + f];
            float h1v = g_h[(size_t)s1 * NH + f];
            float h2  = g_h[(size_t)s2 * NH + f];
            float h3  = g_h[(size_t)s3 * NH + f];
            acc = fmaf(w0, h0, acc);
            acc = fmaf(w1, h1v, acc);
            acc = fmaf(w2, h2, acc);
            acc = fmaf(w3, h3, acc);
        }
        for (; j < n; j++)
            acc = fmaf(snrm[j], g_h[(size_t)scol[j] * NH + f], acc);
        __syncthreads();
    }
    float di = g_dinv[i];
    float v  = fmaf(di, acc, di * di * g_h[(size_t)i * NH + f]) + b1[f];
    g_h1[(size_t)i * NH + f] = fmaxf(v, 0.f);
}

// ------------------- GEMM2: g_g = h1[NN,256] @ W2[256,7] --------------------
__global__ void gemm2_kernel(const float* __restrict__ W2) {
    __shared__ float sW[NH * NC];
    const int tid = threadIdx.x;
    for (int t = tid; t < NH * NC; t += 256) sW[t] = W2[t];
    __syncthreads();
    const int lane = tid & 31;
    const int node = blockIdx.x * 8 + (tid >> 5);
    float p[NC];
    #pragma unroll
    for (int j = 0; j < NC; j++) p[j] = 0.f;
    #pragma unroll
    for (int u = 0; u < 8; u++) {
        int k = u * 32 + lane;
        float v = g_h1[(size_t)node * NH + k];
        #pragma unroll
        for (int j = 0; j < NC; j++) p[j] = fmaf(v, sW[k * NC + j], p[j]);
    }
    #pragma unroll
    for (int o = 16; o > 0; o >>= 1)
        #pragma unroll
        for (int j = 0; j < NC; j++) p[j] += __shfl_down_sync(0xffffffffu, p[j], o);
    if (lane == 0) {
        #pragma unroll
        for (int j = 0; j < NC; j++) g_g[node * 8 + j] = p[j];
        g_g[node * 8 + 7] = 0.f;
    }
}

// ------------------- aggregation layer 2 (7-wide, CSR gather) ---------------
__global__ void agg2_kernel(const float* __restrict__ b2, float* __restrict__ out) {
    const int tid  = threadIdx.x;
    const int node = blockIdx.x * 32 + (tid >> 3);
    const int j    = tid & 7;
    if (node >= NN) return;
    const int start = g_rowptr[node], end = g_rowptr[node + 1];
    float acc = 0.f;
    for (int p = start; p < end; p++) {
        int s = g_col[p];
        acc = fmaf(g_dinv[s], g_g[s * 8 + j], acc);
    }
    float di = g_dinv[node];
    float v  = fmaf(di, acc, di * di * g_g[node * 8 + j]);
    if (j < NC) out[node * NC + j] = v + b2[j];
}

// ------------------- launch --------------------------------------------------
extern "C" void kernel_launch(void* const* d_in, const int* in_sizes, int n_in,
                              void* d_out, int out_size) {
    const float* x    = (const float*)d_in[0];
    const int*   ei32 = (const int*)d_in[1];   // int32 OR int64 (auto-detected)
    const float* W1   = (const float*)d_in[2];
    const float* b1   = (const float*)d_in[3];
    const float* W2   = (const float*)d_in[4];
    const float* b2   = (const float*)d_in[5];
    float*       out  = (float*)d_out;

    detect_kernel<<<1, 32>>>(ei32);
    zero_cnt_kernel<<<(NN + 255) / 256, 256>>>();
    count_kernel<<<(NE + 255) / 256, 256>>>(ei32);

    // gemm1 placed 4th so the ncu capture window (-s 5 -c 1) lands on it.
    dim3 g1(2, (NN + 127) / 128);   // (n-tiles, m-tiles)
    mma_gemm1_kernel<<<g1, 256>>>(x, W1);

    scanA_kernel<<<SCAN_NB, 256>>>();
    scanB_kernel<<<1, 256>>>();
    scanC_kernel<<<SCAN_NB, 256>>>();
    fill_kernel<<<(NE + 255) / 256, 256>>>(ei32);

    agg1_kernel<<<NN, 256>>>(b1);
    gemm2_kernel<<<NN / 8, 256>>>(W2);
    agg2_kernel<<<(NN + 31) / 32, 256>>>(b2, out);
}